// round 5
// baseline (speedup 1.0000x reference)
#include <cuda_runtime.h>
#include <cstdint>

#define BB 8

// Scratch
__device__ float2 g_X1[BB * 16 * 256 * 32];   // [b][k][y][c]
__device__ float2 g_X2[BB * 16 * 32 * 32];    // [bk][h'][c]
__device__ float4 g_SD[BB * 16 * 17 * 32];    // [bk][p][o] (Sr,Si,Dr,Di) pre-scaled
__device__ float2 g_G [BB * 256 * 16 * 32];   // [b][y][k][o]
__device__ float2 g_Wt[16 * 32 * 32 * 32];    // [k][h'][c][o]

// ---------------------------------------------------------------------------
// Compile-time trig table -> FFMA immediates after full unroll.
// ---------------------------------------------------------------------------
struct Trig { float c[256]; float s[256]; };

__host__ __device__ constexpr double tp_cos(double x) {
    double x2 = x * x, t = 1.0, s = 1.0;
    for (int n = 1; n <= 12; n++) { t *= -x2 / double((2 * n - 1) * (2 * n)); s += t; }
    return s;
}
__host__ __device__ constexpr double tp_sin(double x) {
    double x2 = x * x, t = x, s = x;
    for (int n = 1; n <= 12; n++) { t *= -x2 / double((2 * n) * (2 * n + 1)); s += t; }
    return s;
}
__host__ __device__ constexpr Trig make_trig() {
    Trig tr{};
    for (int i = 0; i < 256; i++) {
        int q = i >> 6, r = i & 63;
        double x = 3.14159265358979323846 * double(r) / 128.0;
        double c = tp_cos(x), s = tp_sin(x);
        tr.c[i] = (float)(q == 0 ? c : q == 1 ? -s : q == 2 ? -c :  s);
        tr.s[i] = (float)(q == 0 ? s : q == 1 ?  c : q == 2 ? -s : -c);
    }
    return tr;
}

// ---------------------------------------------------------------------------
// k0: weight reorder (coalesced reads, scattered 8B stores).
// ---------------------------------------------------------------------------
__global__ void k0_reorder_w(const float* __restrict__ wr, const float* __restrict__ wi) {
    int idx = blockIdx.x * 256 + threadIdx.x;
    int m2 = idx & 15;
    int m1 = (idx >> 4) & 15;
    int o  = (idx >> 8) & 31;
    int c  = (idx >> 13) & 31;
    int w  = idx >> 18;
    int dst = ((m2 * 32 + (w * 16 + m1)) * 32 + c) * 32 + o;
    g_Wt[dst] = make_float2(wr[idx], wi[idx]);
}

// ---------------------------------------------------------------------------
// k1: forward W-DFT. 2 warps per row (k-halves), lane = c.
// ---------------------------------------------------------------------------
template<int K0>
__device__ __forceinline__ void fwdW(const float* __restrict__ p, float2* __restrict__ o) {
    constexpr Trig TR = make_trig();
    float re[8], im[8];
    float v0 = p[0], v128 = p[128 * 32];
    float pe = v0 + v128, po = v0 - v128;
#pragma unroll
    for (int j = 0; j < 8; j++) { re[j] = ((K0 + j) & 1) ? po : pe; im[j] = 0.f; }

#pragma unroll
    for (int xp = 1; xp <= 127; xp++) {
        float a = p[xp * 32];
        float b = p[(256 - xp) * 32];
        float s = a + b, d = a - b;
#pragma unroll
        for (int j = 0; j < 8; j++) {
            const int k = K0 + j, id = (k * xp) & 255;
            re[j] = fmaf(s, TR.c[id], re[j]);
            if (k) im[j] = fmaf(d, -TR.s[id], im[j]);
        }
    }
#pragma unroll
    for (int j = 0; j < 8; j++) o[(size_t)(K0 + j) * 8192] = make_float2(re[j], im[j]);
}

__global__ void __launch_bounds__(256) k1_fwd_w(const float* __restrict__ x) {
    int t = threadIdx.x, c = t & 31, w = t >> 5;
    int row = blockIdx.x * 4 + (w >> 1);
    const float* __restrict__ p = x + (size_t)row * 8192 + c;
    int b_ = row >> 8, y = row & 255;
    float2* o = g_X1 + ((size_t)(b_ * 16) * 256 + y) * 32 + c;
    if ((w & 1) == 0) fwdW<0>(p, o);
    else              fwdW<8>(p, o);
}

// ---------------------------------------------------------------------------
// k2a: forward H-DFT. Block selects m-case (I$-uniform); warps take distinct bk.
// ---------------------------------------------------------------------------
template<int M0, int MC>
__device__ __forceinline__ void phaseA(const float2* __restrict__ xv,
                                       float2* __restrict__ X2, int c) {
    constexpr Trig TR = make_trig();
    float Pr[MC], Pi[MC], Qr[MC], Qi[MC];
    float2 v0 = xv[c], v128 = xv[128 * 32 + c];
#pragma unroll
    for (int j = 0; j < MC; j++) {
        const int m = M0 + 8 * j;
        Pr[j] = (m & 1) ? v0.x - v128.x : v0.x + v128.x;
        Pi[j] = (m & 1) ? v0.y - v128.y : v0.y + v128.y;
        Qr[j] = 0.f; Qi[j] = 0.f;
    }
#pragma unroll
    for (int yp = 1; yp <= 127; yp++) {
        float2 a = xv[yp * 32 + c];
        float2 b = xv[(256 - yp) * 32 + c];
        float sx = a.x + b.x, sy = a.y + b.y;
        float dx = a.x - b.x, dy = a.y - b.y;
#pragma unroll
        for (int j = 0; j < MC; j++) {
            const int m = M0 + 8 * j, id = (m * yp) & 255;
            Pr[j] = fmaf(sx, TR.c[id], Pr[j]);
            Pi[j] = fmaf(sy, TR.c[id], Pi[j]);
            if (m) {
                Qr[j] = fmaf(dx, TR.s[id], Qr[j]);
                Qi[j] = fmaf(dy, TR.s[id], Qi[j]);
            }
        }
    }
#pragma unroll
    for (int j = 0; j < MC; j++) {
        const int m = M0 + 8 * j;
        if (m == 0) {
            X2[c] = make_float2(Pr[j], Pi[j]);
        } else if (m == 16) {
            X2[16 * 32 + c] = make_float2(Pr[j] - Qi[j], Pi[j] + Qr[j]);
        } else {
            X2[m * 32 + c]        = make_float2(Pr[j] + Qi[j], Pi[j] - Qr[j]);
            X2[(32 - m) * 32 + c] = make_float2(Pr[j] - Qi[j], Pi[j] + Qr[j]);
        }
    }
}

__global__ void __launch_bounds__(256) k2a_fwdh() {
    int t = threadIdx.x, w = t >> 5, c = t & 31;
    int mcase = blockIdx.x >> 4;        // 0..7 (16 consecutive bids share a region)
    int grp   = blockIdx.x & 15;
    int bk = grp * 8 + w;
    const float2* __restrict__ xv = g_X1 + (size_t)bk * 8192;
    float2* __restrict__ X2 = g_X2 + (size_t)bk * 1024;
    switch (mcase) {
        case 0: phaseA<0, 3>(xv, X2, c); break;   // m = 0, 8, 16
        case 1: phaseA<1, 2>(xv, X2, c); break;
        case 2: phaseA<2, 2>(xv, X2, c); break;
        case 3: phaseA<3, 2>(xv, X2, c); break;
        case 4: phaseA<4, 2>(xv, X2, c); break;
        case 5: phaseA<5, 2>(xv, X2, c); break;
        case 6: phaseA<6, 2>(xv, X2, c); break;
        default: phaseA<7, 2>(xv, X2, c); break;
    }
}

// ---------------------------------------------------------------------------
// k2c: einsum over c + pair-combine + scale -> g_SD. Loop-based, tiny code.
// ---------------------------------------------------------------------------
__global__ void __launch_bounds__(256) k2c_einsum() {
    __shared__ float2 X2s[1024];
    __shared__ float2 OB[1024];
    int t = threadIdx.x, w = t >> 5, c = t & 31;
    int bk = blockIdx.x, k = bk & 15;

    const float4* __restrict__ src = (const float4*)(g_X2 + (size_t)bk * 1024);
    float4* dst = (float4*)X2s;
#pragma unroll
    for (int i = t; i < 512; i += 256) dst[i] = src[i];
    __syncthreads();

    const float2* __restrict__ wtk = g_Wt + (size_t)k * 32768;
#pragma unroll
    for (int j = 0; j < 4; j++) {
        int h = w * 4 + j;
        float ar = 0.f, ai = 0.f;
        const float2* __restrict__ xr = X2s + h * 32;
        const float2* __restrict__ wrow = wtk + (size_t)h * 1024 + c;
#pragma unroll
        for (int cc = 0; cc < 32; cc++) {
            float2 xx = xr[cc];
            float2 ww = wrow[cc * 32];
            ar = fmaf(xx.x, ww.x, ar); ar = fmaf(-xx.y, ww.y, ar);
            ai = fmaf(xx.x, ww.y, ai); ai = fmaf( xx.y, ww.x, ai);
        }
        OB[h * 32 + c] = make_float2(ar, ai);
    }
    __syncthreads();

    float sc = (k == 0) ? (1.0f / 65536.0f) : (2.0f / 65536.0f);
    for (int tt = t; tt < 17 * 32; tt += 256) {
        int p = tt >> 5, o = tt & 31;
        float2 A = OB[p * 32 + o];
        float4 r;
        if (p == 0 || p == 16) {
            r = make_float4(A.x * sc, A.y * sc, -A.x * sc, -A.y * sc);
        } else {
            float2 Bv = OB[(32 - p) * 32 + o];
            r = make_float4((A.x + Bv.x) * sc, (A.y + Bv.y) * sc,
                            (A.x - Bv.x) * sc, (A.y - Bv.y) * sc);
        }
        g_SD[(size_t)bk * 544 + tt] = r;
    }
}

// ---------------------------------------------------------------------------
// k2b: inverse H. Block selects yp-range (I$-uniform); warps take distinct bk.
// ---------------------------------------------------------------------------
template<int Y0, int Y1>
__device__ __forceinline__ void invH(const float4* __restrict__ sd,
                                     float2* __restrict__ g) {
    constexpr Trig TR = make_trig();
#pragma unroll
    for (int yp = Y0; yp < Y1; yp++) {
        float U1 = 0.f, U2 = 0.f, V1 = 0.f, V2 = 0.f;
#pragma unroll
        for (int p = 0; p < 17; p++) {
            const int id = (p * yp) & 255;
            U1 = fmaf(sd[p].x, TR.c[id], U1);
            U2 = fmaf(sd[p].y, TR.c[id], U2);
            if (p) {
                V1 = fmaf(sd[p].w, TR.s[id], V1);
                V2 = fmaf(sd[p].z, TR.s[id], V2);
            }
        }
        g[(size_t)yp * 512] = make_float2(U1 - V1, U2 + V2);
        if (yp != 0 && yp != 128)
            g[(size_t)(256 - yp) * 512] = make_float2(U1 + V1, U2 - V2);
    }
}

__global__ void __launch_bounds__(256) k2b_invh() {
    int t = threadIdx.x, w = t >> 5, c = t & 31;
    int range = blockIdx.x >> 4;        // 16 consecutive bids share a region
    int grp   = blockIdx.x & 15;
    int bk = grp * 8 + w;

    float4 sd[17];
#pragma unroll
    for (int p = 0; p < 17; p++) sd[p] = g_SD[(size_t)bk * 544 + p * 32 + c];

    float2* __restrict__ g = g_G + ((size_t)(bk >> 4) * 4096 + (bk & 15)) * 32 + c;
    switch (range) {
        case 0: invH<0,   16>(sd, g); break;
        case 1: invH<16,  32>(sd, g); break;
        case 2: invH<32,  48>(sd, g); break;
        case 3: invH<48,  64>(sd, g); break;
        case 4: invH<64,  80>(sd, g); break;
        case 5: invH<80,  96>(sd, g); break;
        case 6: invH<96, 112>(sd, g); break;
        default: invH<112, 129>(sd, g); break;
    }
}

// ---------------------------------------------------------------------------
// k3: inverse W. 2 warps per row (xp-halves), lane = o.
// ---------------------------------------------------------------------------
template<int X0, int X1>
__device__ __forceinline__ void invW(const float* __restrict__ Gr,
                                     const float* __restrict__ Gi,
                                     float* __restrict__ ob) {
    constexpr Trig TR = make_trig();
#pragma unroll
    for (int xp = X0; xp < X1; xp++) {
        float A = 0.f, B = 0.f;
#pragma unroll
        for (int k = 0; k < 16; k++) {
            const int id = (k * xp) & 255;
            A = fmaf(Gr[k], TR.c[id], A);
            if (k) B = fmaf(Gi[k], TR.s[id], B);
        }
        ob[xp * 32] = A - B;
        if (xp != 0 && xp != 128)
            ob[(256 - xp) * 32] = A + B;
    }
}

__global__ void __launch_bounds__(256) k3_inv_w(float* __restrict__ out) {
    int t = threadIdx.x, o = t & 31, w = t >> 5;
    int row = blockIdx.x * 4 + (w >> 1);
    const float2* __restrict__ g = g_G + (size_t)row * 512 + o;

    float Gr[16], Gi[16];
#pragma unroll
    for (int k = 0; k < 16; k++) { float2 v = g[k * 32]; Gr[k] = v.x; Gi[k] = v.y; }

    float* __restrict__ ob = out + (size_t)row * 8192 + o;
    if ((w & 1) == 0) invW<0, 65>(Gr, Gi, ob);
    else              invW<65, 129>(Gr, Gi, ob);
}

// ---------------------------------------------------------------------------
extern "C" void kernel_launch(void* const* d_in, const int* in_sizes, int n_in,
                              void* d_out, int out_size) {
    const float* x  = (const float*)d_in[0];
    const float* wr = (const float*)d_in[1];
    const float* wi = (const float*)d_in[2];
    float* out = (float*)d_out;

    k0_reorder_w<<<2048, 256>>>(wr, wi);
    k1_fwd_w   <<<512, 256>>>(x);
    k2a_fwdh   <<<128, 256>>>();
    k2c_einsum <<<128, 256>>>();
    k2b_invh   <<<128, 256>>>();
    k3_inv_w   <<<512, 256>>>(out);
}

// round 7
// speedup vs baseline: 1.0439x; 1.0439x over previous
#include <cuda_runtime.h>
#include <cstdint>

#define BB 8

// Scratch
__device__ float2 g_X1[BB * 16 * 256 * 32];   // [b][k][y][c]
__device__ float2 g_X2[BB * 16 * 32 * 32];    // [bk][h'][c]
__device__ float4 g_SD[BB * 16 * 17 * 32];    // [bk][p][o] (Sr,Si,Dr,Di) pre-scaled
__device__ float2 g_G [BB * 256 * 16 * 32];   // [b][y][k][o]
__device__ float2 g_Wt[16 * 32 * 32 * 32];    // [k][h'][c][o]

// ---------------------------------------------------------------------------
// Compile-time trig table -> FFMA immediates after full unroll.
// ---------------------------------------------------------------------------
struct Trig { float c[256]; float s[256]; };

__host__ __device__ constexpr double tp_cos(double x) {
    double x2 = x * x, t = 1.0, s = 1.0;
    for (int n = 1; n <= 12; n++) { t *= -x2 / double((2 * n - 1) * (2 * n)); s += t; }
    return s;
}
__host__ __device__ constexpr double tp_sin(double x) {
    double x2 = x * x, t = x, s = x;
    for (int n = 1; n <= 12; n++) { t *= -x2 / double((2 * n) * (2 * n + 1)); s += t; }
    return s;
}
__host__ __device__ constexpr Trig make_trig() {
    Trig tr{};
    for (int i = 0; i < 256; i++) {
        int q = i >> 6, r = i & 63;
        double x = 3.14159265358979323846 * double(r) / 128.0;
        double c = tp_cos(x), s = tp_sin(x);
        tr.c[i] = (float)(q == 0 ? c : q == 1 ? -s : q == 2 ? -c :  s);
        tr.s[i] = (float)(q == 0 ? s : q == 1 ?  c : q == 2 ? -s : -c);
    }
    return tr;
}

// ---------------------------------------------------------------------------
// k0: weight reorder (coalesced reads, scattered 8B stores).
// ---------------------------------------------------------------------------
__global__ void k0_reorder_w(const float* __restrict__ wr, const float* __restrict__ wi) {
    int idx = blockIdx.x * 256 + threadIdx.x;
    int m2 = idx & 15;
    int m1 = (idx >> 4) & 15;
    int o  = (idx >> 8) & 31;
    int c  = (idx >> 13) & 31;
    int w  = idx >> 18;
    int dst = ((m2 * 32 + (w * 16 + m1)) * 32 + c) * 32 + o;
    g_Wt[dst] = make_float2(wr[idx], wi[idx]);
}

// ---------------------------------------------------------------------------
// k1: forward W-DFT. Block parity selects k-half (I$-uniform per block);
//     warp selects row. Rows read twice -> second read is L2-hit.
// ---------------------------------------------------------------------------
template<int K0>
__device__ __forceinline__ void fwdW(const float* __restrict__ p, float2* __restrict__ o) {
    constexpr Trig TR = make_trig();
    float re[8], im[8];
    float v0 = p[0], v128 = p[128 * 32];
    float pe = v0 + v128, po = v0 - v128;
#pragma unroll
    for (int j = 0; j < 8; j++) { re[j] = ((K0 + j) & 1) ? po : pe; im[j] = 0.f; }

#pragma unroll
    for (int xp = 1; xp <= 127; xp++) {
        float a = p[xp * 32];
        float b = p[(256 - xp) * 32];
        float s = a + b, d = a - b;
#pragma unroll
        for (int j = 0; j < 8; j++) {
            const int k = K0 + j, id = (k * xp) & 255;
            re[j] = fmaf(s, TR.c[id], re[j]);
            if (k) im[j] = fmaf(d, -TR.s[id], im[j]);
        }
    }
#pragma unroll
    for (int j = 0; j < 8; j++) o[(size_t)(K0 + j) * 8192] = make_float2(re[j], im[j]);
}

__global__ void __launch_bounds__(256) k1_fwd_w(const float* __restrict__ x) {
    int t = threadIdx.x, c = t & 31, w = t >> 5;
    int half = blockIdx.x & 1;
    int row = (blockIdx.x >> 1) * 8 + w;          // 8 rows per block
    const float* __restrict__ p = x + (size_t)row * 8192 + c;
    int b_ = row >> 8, y = row & 255;
    float2* o = g_X1 + ((size_t)(b_ * 16) * 256 + y) * 32 + c;
    if (half == 0) fwdW<0>(p, o);
    else           fwdW<8>(p, o);
}

// ---------------------------------------------------------------------------
// k2a: forward H-DFT. Block selects m-case (I$-uniform); warps take distinct bk.
// ---------------------------------------------------------------------------
template<int M0, int MC>
__device__ __forceinline__ void phaseA(const float2* __restrict__ xv,
                                       float2* __restrict__ X2, int c) {
    constexpr Trig TR = make_trig();
    float Pr[MC], Pi[MC], Qr[MC], Qi[MC];
    float2 v0 = xv[c], v128 = xv[128 * 32 + c];
#pragma unroll
    for (int j = 0; j < MC; j++) {
        const int m = M0 + 8 * j;
        Pr[j] = (m & 1) ? v0.x - v128.x : v0.x + v128.x;
        Pi[j] = (m & 1) ? v0.y - v128.y : v0.y + v128.y;
        Qr[j] = 0.f; Qi[j] = 0.f;
    }
#pragma unroll
    for (int yp = 1; yp <= 127; yp++) {
        float2 a = xv[yp * 32 + c];
        float2 b = xv[(256 - yp) * 32 + c];
        float sx = a.x + b.x, sy = a.y + b.y;
        float dx = a.x - b.x, dy = a.y - b.y;
#pragma unroll
        for (int j = 0; j < MC; j++) {
            const int m = M0 + 8 * j, id = (m * yp) & 255;
            Pr[j] = fmaf(sx, TR.c[id], Pr[j]);
            Pi[j] = fmaf(sy, TR.c[id], Pi[j]);
            if (m) {
                Qr[j] = fmaf(dx, TR.s[id], Qr[j]);
                Qi[j] = fmaf(dy, TR.s[id], Qi[j]);
            }
        }
    }
#pragma unroll
    for (int j = 0; j < MC; j++) {
        const int m = M0 + 8 * j;
        if (m == 0) {
            X2[c] = make_float2(Pr[j], Pi[j]);
        } else if (m == 16) {
            X2[16 * 32 + c] = make_float2(Pr[j] - Qi[j], Pi[j] + Qr[j]);
        } else {
            X2[m * 32 + c]        = make_float2(Pr[j] + Qi[j], Pi[j] - Qr[j]);
            X2[(32 - m) * 32 + c] = make_float2(Pr[j] - Qi[j], Pi[j] + Qr[j]);
        }
    }
}

__global__ void __launch_bounds__(256) k2a_fwdh() {
    int t = threadIdx.x, w = t >> 5, c = t & 31;
    int mcase = blockIdx.x >> 4;
    int grp   = blockIdx.x & 15;
    int bk = grp * 8 + w;
    const float2* __restrict__ xv = g_X1 + (size_t)bk * 8192;
    float2* __restrict__ X2 = g_X2 + (size_t)bk * 1024;
    switch (mcase) {
        case 0: phaseA<0, 3>(xv, X2, c); break;   // m = 0, 8, 16
        case 1: phaseA<1, 2>(xv, X2, c); break;
        case 2: phaseA<2, 2>(xv, X2, c); break;
        case 3: phaseA<3, 2>(xv, X2, c); break;
        case 4: phaseA<4, 2>(xv, X2, c); break;
        case 5: phaseA<5, 2>(xv, X2, c); break;
        case 6: phaseA<6, 2>(xv, X2, c); break;
        default: phaseA<7, 2>(xv, X2, c); break;
    }
}

// ---------------------------------------------------------------------------
// k2c: einsum + pair-combine. Block per bk, 1024 threads: warp = h, lane = o.
// ---------------------------------------------------------------------------
__global__ void __launch_bounds__(1024) k2c_einsum() {
    __shared__ float2 X2s[1024];        // [h][c]
    __shared__ float2 OB[1024];         // [h][o]
    int t = threadIdx.x, h = t >> 5, o = t & 31;
    int bk = blockIdx.x, k = bk & 15;

    X2s[t] = g_X2[(size_t)bk * 1024 + t];
    __syncthreads();

    const float2* __restrict__ wrow = g_Wt + (size_t)k * 32768 + (size_t)h * 1024 + o;
    const float2* __restrict__ xr = X2s + h * 32;
    float ar = 0.f, ai = 0.f;
#pragma unroll
    for (int cc = 0; cc < 32; cc++) {
        float2 xx = xr[cc];             // uniform per warp -> LDS broadcast
        float2 ww = wrow[cc * 32];      // coalesced 256B, independent -> high MLP
        ar = fmaf(xx.x, ww.x, ar); ar = fmaf(-xx.y, ww.y, ar);
        ai = fmaf(xx.x, ww.y, ai); ai = fmaf( xx.y, ww.x, ai);
    }
    OB[t] = make_float2(ar, ai);
    __syncthreads();

    float sc = (k == 0) ? (1.0f / 65536.0f) : (2.0f / 65536.0f);
    if (t < 17 * 32) {
        int p = t >> 5;
        float2 A = OB[t];
        float4 r;
        if (p == 0 || p == 16) {
            r = make_float4(A.x * sc, A.y * sc, -A.x * sc, -A.y * sc);
        } else {
            float2 Bv = OB[(32 - p) * 32 + o];
            r = make_float4((A.x + Bv.x) * sc, (A.y + Bv.y) * sc,
                            (A.x - Bv.x) * sc, (A.y - Bv.y) * sc);
        }
        g_SD[(size_t)bk * 544 + t] = r;
    }
}

// ---------------------------------------------------------------------------
// k2b: inverse H. Block selects yp-range (I$-uniform); warps take distinct bk.
// ---------------------------------------------------------------------------
template<int Y0, int Y1>
__device__ __forceinline__ void invH(const float4* __restrict__ sd,
                                     float2* __restrict__ g) {
    constexpr Trig TR = make_trig();
#pragma unroll
    for (int yp = Y0; yp < Y1; yp++) {
        float U1 = 0.f, U2 = 0.f, V1 = 0.f, V2 = 0.f;
#pragma unroll
        for (int p = 0; p < 17; p++) {
            const int id = (p * yp) & 255;
            U1 = fmaf(sd[p].x, TR.c[id], U1);
            U2 = fmaf(sd[p].y, TR.c[id], U2);
            if (p) {
                V1 = fmaf(sd[p].w, TR.s[id], V1);
                V2 = fmaf(sd[p].z, TR.s[id], V2);
            }
        }
        g[(size_t)yp * 512] = make_float2(U1 - V1, U2 + V2);
        if (yp != 0 && yp != 128)
            g[(size_t)(256 - yp) * 512] = make_float2(U1 + V1, U2 - V2);
    }
}

__global__ void __launch_bounds__(256) k2b_invh() {
    int t = threadIdx.x, w = t >> 5, c = t & 31;
    int range = blockIdx.x >> 4;
    int grp   = blockIdx.x & 15;
    int bk = grp * 8 + w;

    float4 sd[17];
#pragma unroll
    for (int p = 0; p < 17; p++) sd[p] = g_SD[(size_t)bk * 544 + p * 32 + c];

    float2* __restrict__ g = g_G + ((size_t)(bk >> 4) * 4096 + (bk & 15)) * 32 + c;
    switch (range) {
        case 0: invH<0,   16>(sd, g); break;
        case 1: invH<16,  32>(sd, g); break;
        case 2: invH<32,  48>(sd, g); break;
        case 3: invH<48,  64>(sd, g); break;
        case 4: invH<64,  80>(sd, g); break;
        case 5: invH<80,  96>(sd, g); break;
        case 6: invH<96, 112>(sd, g); break;
        default: invH<112, 129>(sd, g); break;
    }
}

// ---------------------------------------------------------------------------
// k3: inverse W. Block parity selects xp-half (I$-uniform); warp selects row.
// ---------------------------------------------------------------------------
template<int X0, int X1>
__device__ __forceinline__ void invW(const float* __restrict__ Gr,
                                     const float* __restrict__ Gi,
                                     float* __restrict__ ob) {
    constexpr Trig TR = make_trig();
#pragma unroll
    for (int xp = X0; xp < X1; xp++) {
        float A = 0.f, B = 0.f;
#pragma unroll
        for (int k = 0; k < 16; k++) {
            const int id = (k * xp) & 255;
            A = fmaf(Gr[k], TR.c[id], A);
            if (k) B = fmaf(Gi[k], TR.s[id], B);
        }
        ob[xp * 32] = A - B;
        if (xp != 0 && xp != 128)
            ob[(256 - xp) * 32] = A + B;
    }
}

__global__ void __launch_bounds__(256) k3_inv_w(float* __restrict__ out) {
    int t = threadIdx.x, o = t & 31, w = t >> 5;
    int half = blockIdx.x & 1;
    int row = (blockIdx.x >> 1) * 8 + w;
    const float2* __restrict__ g = g_G + (size_t)row * 512 + o;

    float Gr[16], Gi[16];
#pragma unroll
    for (int k = 0; k < 16; k++) { float2 v = g[k * 32]; Gr[k] = v.x; Gi[k] = v.y; }

    float* __restrict__ ob = out + (size_t)row * 8192 + o;
    if (half == 0) invW<0, 65>(Gr, Gi, ob);
    else           invW<65, 129>(Gr, Gi, ob);
}

// ---------------------------------------------------------------------------
extern "C" void kernel_launch(void* const* d_in, const int* in_sizes, int n_in,
                              void* d_out, int out_size) {
    const float* x  = (const float*)d_in[0];
    const float* wr = (const float*)d_in[1];
    const float* wi = (const float*)d_in[2];
    float* out = (float*)d_out;

    k0_reorder_w<<<2048, 256>>>(wr, wi);
    k1_fwd_w   <<<512, 256>>>(x);
    k2a_fwdh   <<<128, 256>>>();
    k2c_einsum <<<128, 1024>>>();
    k2b_invh   <<<128, 256>>>();
    k3_inv_w   <<<512, 256>>>(out);
}

// round 8
// speedup vs baseline: 1.2894x; 1.2351x over previous
#include <cuda_runtime.h>
#include <cstdint>

#define BB 8

// Scratch
__device__ float2 g_X1[BB * 16 * 256 * 32];   // [b][k][y][c]
__device__ float2 g_X2[BB * 16 * 32 * 32];    // [bk][h'][c]
__device__ float2 g_OB[BB * 16 * 32 * 32];    // [bk][h'][o]  scaled einsum output
__device__ float2 g_G [BB * 256 * 16 * 32];   // [b][y][k][o]
__device__ float2 g_Wt[16 * 32 * 32 * 32];    // [k][h'][c][o]

// ---------------------------------------------------------------------------
// Compile-time trig table -> FFMA immediates after full unroll.
// ---------------------------------------------------------------------------
struct Trig { float c[256]; float s[256]; };

__host__ __device__ constexpr double tp_cos(double x) {
    double x2 = x * x, t = 1.0, s = 1.0;
    for (int n = 1; n <= 12; n++) { t *= -x2 / double((2 * n - 1) * (2 * n)); s += t; }
    return s;
}
__host__ __device__ constexpr double tp_sin(double x) {
    double x2 = x * x, t = x, s = x;
    for (int n = 1; n <= 12; n++) { t *= -x2 / double((2 * n) * (2 * n + 1)); s += t; }
    return s;
}
__host__ __device__ constexpr Trig make_trig() {
    Trig tr{};
    for (int i = 0; i < 256; i++) {
        int q = i >> 6, r = i & 63;
        double x = 3.14159265358979323846 * double(r) / 128.0;
        double c = tp_cos(x), s = tp_sin(x);
        tr.c[i] = (float)(q == 0 ? c : q == 1 ? -s : q == 2 ? -c :  s);
        tr.s[i] = (float)(q == 0 ? s : q == 1 ?  c : q == 2 ? -s : -c);
    }
    return tr;
}

// ---------------------------------------------------------------------------
// k0: weight reorder (coalesced reads, scattered 8B stores).
//   Launched right before k2c so g_Wt is L2-resident when consumed.
// ---------------------------------------------------------------------------
__global__ void k0_reorder_w(const float* __restrict__ wr, const float* __restrict__ wi) {
    int idx = blockIdx.x * 256 + threadIdx.x;
    int m2 = idx & 15;
    int m1 = (idx >> 4) & 15;
    int o  = (idx >> 8) & 31;
    int c  = (idx >> 13) & 31;
    int w  = idx >> 18;
    int dst = ((m2 * 32 + (w * 16 + m1)) * 32 + c) * 32 + o;
    g_Wt[dst] = make_float2(wr[idx], wi[idx]);
}

// ---------------------------------------------------------------------------
// k1: forward W-DFT. One warp per row, all 16 k-bins in registers.
//     Single code region for every warp (best measured issue rate).
// ---------------------------------------------------------------------------
__global__ void __launch_bounds__(256) k1_fwd_w(const float* __restrict__ x) {
    constexpr Trig TR = make_trig();
    int t = threadIdx.x, c = t & 31;
    int row = blockIdx.x * 8 + (t >> 5);
    const float* __restrict__ p = x + (size_t)row * 8192 + c;

    float re[16], im[16];
    float v0 = p[0], v128 = p[128 * 32];
    float pe = v0 + v128, po = v0 - v128;
#pragma unroll
    for (int k = 0; k < 16; k++) { re[k] = (k & 1) ? po : pe; im[k] = 0.f; }

#pragma unroll
    for (int xp = 1; xp <= 127; xp++) {
        float a = p[xp * 32];
        float b = p[(256 - xp) * 32];
        float s = a + b, d = a - b;
#pragma unroll
        for (int k = 0; k < 16; k++) {
            const int id = (k * xp) & 255;
            re[k] = fmaf(s, TR.c[id], re[k]);
            if (k) im[k] = fmaf(d, -TR.s[id], im[k]);
        }
    }

    int b_ = row >> 8, y = row & 255;
    float2* o = g_X1 + ((size_t)(b_ * 16) * 256 + y) * 32 + c;
#pragma unroll
    for (int k = 0; k < 16; k++) o[(size_t)k * 8192] = make_float2(re[k], im[k]);
}

// ---------------------------------------------------------------------------
// k2a: forward H-DFT. Block selects m-case (I$-uniform); warps take distinct bk.
// ---------------------------------------------------------------------------
template<int M0, int MC>
__device__ __forceinline__ void phaseA(const float2* __restrict__ xv,
                                       float2* __restrict__ X2, int c) {
    constexpr Trig TR = make_trig();
    float Pr[MC], Pi[MC], Qr[MC], Qi[MC];
    float2 v0 = xv[c], v128 = xv[128 * 32 + c];
#pragma unroll
    for (int j = 0; j < MC; j++) {
        const int m = M0 + 8 * j;
        Pr[j] = (m & 1) ? v0.x - v128.x : v0.x + v128.x;
        Pi[j] = (m & 1) ? v0.y - v128.y : v0.y + v128.y;
        Qr[j] = 0.f; Qi[j] = 0.f;
    }
#pragma unroll
    for (int yp = 1; yp <= 127; yp++) {
        float2 a = xv[yp * 32 + c];
        float2 b = xv[(256 - yp) * 32 + c];
        float sx = a.x + b.x, sy = a.y + b.y;
        float dx = a.x - b.x, dy = a.y - b.y;
#pragma unroll
        for (int j = 0; j < MC; j++) {
            const int m = M0 + 8 * j, id = (m * yp) & 255;
            Pr[j] = fmaf(sx, TR.c[id], Pr[j]);
            Pi[j] = fmaf(sy, TR.c[id], Pi[j]);
            if (m) {
                Qr[j] = fmaf(dx, TR.s[id], Qr[j]);
                Qi[j] = fmaf(dy, TR.s[id], Qi[j]);
            }
        }
    }
#pragma unroll
    for (int j = 0; j < MC; j++) {
        const int m = M0 + 8 * j;
        if (m == 0) {
            X2[c] = make_float2(Pr[j], Pi[j]);
        } else if (m == 16) {
            X2[16 * 32 + c] = make_float2(Pr[j] - Qi[j], Pi[j] + Qr[j]);
        } else {
            X2[m * 32 + c]        = make_float2(Pr[j] + Qi[j], Pi[j] - Qr[j]);
            X2[(32 - m) * 32 + c] = make_float2(Pr[j] - Qi[j], Pi[j] + Qr[j]);
        }
    }
}

__global__ void __launch_bounds__(256) k2a_fwdh() {
    int t = threadIdx.x, w = t >> 5, c = t & 31;
    int mcase = blockIdx.x >> 4;
    int grp   = blockIdx.x & 15;
    int bk = grp * 8 + w;
    const float2* __restrict__ xv = g_X1 + (size_t)bk * 8192;
    float2* __restrict__ X2 = g_X2 + (size_t)bk * 1024;
    switch (mcase) {
        case 0: phaseA<0, 3>(xv, X2, c); break;   // m = 0, 8, 16
        case 1: phaseA<1, 2>(xv, X2, c); break;
        case 2: phaseA<2, 2>(xv, X2, c); break;
        case 3: phaseA<3, 2>(xv, X2, c); break;
        case 4: phaseA<4, 2>(xv, X2, c); break;
        case 5: phaseA<5, 2>(xv, X2, c); break;
        case 6: phaseA<6, 2>(xv, X2, c); break;
        default: phaseA<7, 2>(xv, X2, c); break;
    }
}

// ---------------------------------------------------------------------------
// k2c: pure einsum, scaled. Block = (bk, h-half), 512 thr: warp = h, lane = o.
// ---------------------------------------------------------------------------
__global__ void __launch_bounds__(512) k2c_einsum() {
    __shared__ float2 X2s[512];          // [h16][c]
    int t = threadIdx.x, o = t & 31;
    int bk = blockIdx.x >> 1, hh = blockIdx.x & 1;
    int k = bk & 15;
    int h = hh * 16 + (t >> 5);

    X2s[t] = g_X2[(size_t)bk * 1024 + hh * 512 + t];
    __syncthreads();

    const float2* __restrict__ wrow = g_Wt + (size_t)k * 32768 + (size_t)h * 1024 + o;
    const float2* __restrict__ xr = X2s + (t >> 5) * 32;
    float ar = 0.f, ai = 0.f;
#pragma unroll
    for (int cc = 0; cc < 32; cc++) {
        float2 xx = xr[cc];              // uniform per warp -> LDS broadcast
        float2 ww = wrow[cc * 32];       // coalesced, 32 independent -> high MLP
        ar = fmaf(xx.x, ww.x, ar); ar = fmaf(-xx.y, ww.y, ar);
        ai = fmaf(xx.x, ww.y, ai); ai = fmaf( xx.y, ww.x, ai);
    }
    float sc = (k == 0) ? (1.0f / 65536.0f) : (2.0f / 65536.0f);
    g_OB[(size_t)bk * 1024 + h * 32 + o] = make_float2(ar * sc, ai * sc);
}

// ---------------------------------------------------------------------------
// k2b: inverse H. Warp parity selects DATA (real/imag component), not code:
//   cc[p] = e ? Si : Sr,  ss[p] = e ? Dr : Di;  P = sum cc*cos, Q = sum ss*sin;
//   out(yp)[e] = P + sgn*Q, out(256-yp)[e] = P - sgn*Q, sgn = e ? +1 : -1.
//   Single code region per block (range selected by blockIdx). No spills.
// ---------------------------------------------------------------------------
template<int Y0, int Y1>
__device__ __forceinline__ void invH(const float* __restrict__ cc,
                                     const float* __restrict__ ss,
                                     float sgn, float* __restrict__ gf) {
    constexpr Trig TR = make_trig();
#pragma unroll
    for (int yp = Y0; yp < Y1; yp++) {
        float P = 0.f, Q = 0.f;
#pragma unroll
        for (int p = 0; p < 17; p++) {
            const int id = (p * yp) & 255;
            P = fmaf(cc[p], TR.c[id], P);
            if (p) Q = fmaf(ss[p], TR.s[id], Q);
        }
        gf[(size_t)yp * 1024] = fmaf(sgn, Q, P);
        if (yp != 0 && yp != 128)
            gf[(size_t)(256 - yp) * 1024] = fmaf(-sgn, Q, P);
    }
}

__global__ void __launch_bounds__(256) k2b_invh() {
    int t = threadIdx.x, w = t >> 5, c = t & 31;
    int e = w & 1;                        // 0 = real part, 1 = imag part
    int range = blockIdx.x >> 5;          // 8 ranges
    int grp   = blockIdx.x & 31;
    int bk = grp * 4 + (w >> 1);

    const float2* __restrict__ ob = g_OB + (size_t)bk * 1024 + c;
    float cc[17], ss[17];
#pragma unroll
    for (int p = 0; p < 17; p++) {
        float2 A = ob[p * 32];
        if (p == 0 || p == 16) {          // S = A, D = -A
            cc[p] = e ? A.y : A.x;
            ss[p] = e ? -A.x : -A.y;
        } else {
            float2 Bv = ob[(32 - p) * 32];
            cc[p] = e ? (A.y + Bv.y) : (A.x + Bv.x);   // Si or Sr
            ss[p] = e ? (A.x - Bv.x) : (A.y - Bv.y);   // Dr or Di
        }
    }
    float sgn = e ? 1.0f : -1.0f;

    // g_G float view: ((b*256+y)*16 + k)*32 + o, component e
    float* gf = (float*)g_G + (((size_t)(bk >> 4) * 131072 + (bk & 15) * 32 + c) * 2 + e);
    switch (range) {
        case 0: invH<0,   16>(cc, ss, sgn, gf); break;
        case 1: invH<16,  32>(cc, ss, sgn, gf); break;
        case 2: invH<32,  48>(cc, ss, sgn, gf); break;
        case 3: invH<48,  64>(cc, ss, sgn, gf); break;
        case 4: invH<64,  80>(cc, ss, sgn, gf); break;
        case 5: invH<80,  96>(cc, ss, sgn, gf); break;
        case 6: invH<96, 112>(cc, ss, sgn, gf); break;
        default: invH<112, 129>(cc, ss, sgn, gf); break;
    }
}

// ---------------------------------------------------------------------------
// k3: inverse W. Block parity selects xp-half (I$-uniform); warp selects row.
// ---------------------------------------------------------------------------
template<int X0, int X1>
__device__ __forceinline__ void invW(const float* __restrict__ Gr,
                                     const float* __restrict__ Gi,
                                     float* __restrict__ ob) {
    constexpr Trig TR = make_trig();
#pragma unroll
    for (int xp = X0; xp < X1; xp++) {
        float A = 0.f, B = 0.f;
#pragma unroll
        for (int k = 0; k < 16; k++) {
            const int id = (k * xp) & 255;
            A = fmaf(Gr[k], TR.c[id], A);
            if (k) B = fmaf(Gi[k], TR.s[id], B);
        }
        ob[xp * 32] = A - B;
        if (xp != 0 && xp != 128)
            ob[(256 - xp) * 32] = A + B;
    }
}

__global__ void __launch_bounds__(256) k3_inv_w(float* __restrict__ out) {
    int t = threadIdx.x, o = t & 31, w = t >> 5;
    int half = blockIdx.x & 1;
    int row = (blockIdx.x >> 1) * 8 + w;
    const float2* __restrict__ g = g_G + (size_t)row * 512 + o;

    float Gr[16], Gi[16];
#pragma unroll
    for (int k = 0; k < 16; k++) { float2 v = g[k * 32]; Gr[k] = v.x; Gi[k] = v.y; }

    float* __restrict__ ob = out + (size_t)row * 8192 + o;
    if (half == 0) invW<0, 65>(Gr, Gi, ob);
    else           invW<65, 129>(Gr, Gi, ob);
}

// ---------------------------------------------------------------------------
extern "C" void kernel_launch(void* const* d_in, const int* in_sizes, int n_in,
                              void* d_out, int out_size) {
    const float* x  = (const float*)d_in[0];
    const float* wr = (const float*)d_in[1];
    const float* wi = (const float*)d_in[2];
    float* out = (float*)d_out;

    k1_fwd_w   <<<256, 256>>>(x);
    k2a_fwdh   <<<128, 256>>>();
    k0_reorder_w<<<2048, 256>>>(wr, wi);   // fills L2 with g_Wt just before k2c
    k2c_einsum <<<256, 512>>>();
    k2b_invh   <<<256, 256>>>();
    k3_inv_w   <<<512, 256>>>(out);
}

// round 9
// speedup vs baseline: 1.6204x; 1.2567x over previous
#include <cuda_runtime.h>
#include <cstdint>

#define BB 8

// Scratch
__device__ float2 g_X1[BB * 16 * 256 * 32];   // [b][k][y][c]
__device__ float2 g_OB[BB * 16 * 32 * 32];    // [bk][h'][o]  scaled einsum output
__device__ float2 g_G [BB * 256 * 16 * 32];   // [b][y][k][o]
__device__ float2 g_Wt[16 * 32 * 32 * 32];    // [k][h'][c][o]

// ---------------------------------------------------------------------------
// Compile-time trig table -> FFMA immediates after full unroll.
// ---------------------------------------------------------------------------
struct Trig { float c[256]; float s[256]; };

__host__ __device__ constexpr double tp_cos(double x) {
    double x2 = x * x, t = 1.0, s = 1.0;
    for (int n = 1; n <= 12; n++) { t *= -x2 / double((2 * n - 1) * (2 * n)); s += t; }
    return s;
}
__host__ __device__ constexpr double tp_sin(double x) {
    double x2 = x * x, t = x, s = x;
    for (int n = 1; n <= 12; n++) { t *= -x2 / double((2 * n) * (2 * n + 1)); s += t; }
    return s;
}
__host__ __device__ constexpr Trig make_trig() {
    Trig tr{};
    for (int i = 0; i < 256; i++) {
        int q = i >> 6, r = i & 63;
        double x = 3.14159265358979323846 * double(r) / 128.0;
        double c = tp_cos(x), s = tp_sin(x);
        tr.c[i] = (float)(q == 0 ? c : q == 1 ? -s : q == 2 ? -c :  s);
        tr.s[i] = (float)(q == 0 ? s : q == 1 ?  c : q == 2 ? -s : -c);
    }
    return tr;
}

#define SQ2H 0.70710678118654752440f

// ---------------------------------------------------------------------------
// k0: weight reorder (coalesced reads, scattered 8B stores).
// ---------------------------------------------------------------------------
__global__ void k0_reorder_w(const float* __restrict__ wr, const float* __restrict__ wi) {
    int idx = blockIdx.x * 256 + threadIdx.x;
    int m2 = idx & 15;
    int m1 = (idx >> 4) & 15;
    int o  = (idx >> 8) & 31;
    int c  = (idx >> 13) & 31;
    int w  = idx >> 18;
    int dst = ((m2 * 32 + (w * 16 + m1)) * 32 + c) * 32 + o;
    g_Wt[dst] = make_float2(wr[idx], wi[idx]);
}

// ---------------------------------------------------------------------------
// k1: forward W-DFT. One warp per row, all 16 k-bins in registers.
// ---------------------------------------------------------------------------
__global__ void __launch_bounds__(256) k1_fwd_w(const float* __restrict__ x) {
    constexpr Trig TR = make_trig();
    int t = threadIdx.x, c = t & 31;
    int row = blockIdx.x * 8 + (t >> 5);
    const float* __restrict__ p = x + (size_t)row * 8192 + c;

    float re[16], im[16];
    float v0 = p[0], v128 = p[128 * 32];
    float pe = v0 + v128, po = v0 - v128;
#pragma unroll
    for (int k = 0; k < 16; k++) { re[k] = (k & 1) ? po : pe; im[k] = 0.f; }

#pragma unroll
    for (int xp = 1; xp <= 127; xp++) {
        float a = p[xp * 32];
        float b = p[(256 - xp) * 32];
        float s = a + b, d = a - b;
#pragma unroll
        for (int k = 0; k < 16; k++) {
            const int id = (k * xp) & 255;
            re[k] = fmaf(s, TR.c[id], re[k]);
            if (k) im[k] = fmaf(d, -TR.s[id], im[k]);
        }
    }

    int b_ = row >> 8, y = row & 255;
    float2* o = g_X1 + ((size_t)(b_ * 16) * 256 + y) * 32 + c;
#pragma unroll
    for (int k = 0; k < 16; k++) o[(size_t)k * 8192] = make_float2(re[k], im[k]);
}

// ---------------------------------------------------------------------------
// k2ac: fused fwd-H + einsum, one block per bk. Warp w handles y-chunk
//   [32w, 32w+32): partial DFT with (m*u)-immediates (IDENTICAL code for all
//   warps), rotation by cos/sin(pi*m*w/4) (8-entry smem table), smem reduce,
//   X2 assembly, einsum vs L2-warm g_Wt, scaled write to g_OB.
// ---------------------------------------------------------------------------
__global__ void __launch_bounds__(256) k2ac_mid() {
    constexpr Trig TR = make_trig();
    __shared__ float red[4 * 17 * 4 * 32];    // [wq][m][comp][c]  34816 B
    __shared__ float2 X2s[32 * 32];           // [h'][c]           8192 B
    __shared__ float ct8[8], st8[8];

    int t = threadIdx.x, w = t >> 5, c = t & 31;
    int bk = blockIdx.x, k = bk & 15;

    if (t < 8) {
        const float cv[8] = {1.f, SQ2H, 0.f, -SQ2H, -1.f, -SQ2H, 0.f, SQ2H};
        const float sv[8] = {0.f, SQ2H, 1.f, SQ2H, 0.f, -SQ2H, -1.f, -SQ2H};
        ct8[t] = cv[t]; st8[t] = sv[t];
    }

    // --- partial DFT over this warp's y-chunk (same immediates for all w) ---
    const float2* __restrict__ xp = g_X1 + (size_t)bk * 8192 + (size_t)w * 32 * 32 + c;
    float Ar[17], Ai[17], Br[17], Bi[17];
#pragma unroll
    for (int m = 0; m < 17; m++) { Ar[m] = Ai[m] = Br[m] = Bi[m] = 0.f; }
#pragma unroll
    for (int u = 0; u < 32; u++) {
        float2 v = xp[u * 32];
#pragma unroll
        for (int m = 0; m < 17; m++) {
            const int id = (m * u) & 255;
            Ar[m] = fmaf(v.x, TR.c[id], Ar[m]);
            Ai[m] = fmaf(v.y, TR.c[id], Ai[m]);
            if (m) {
                Br[m] = fmaf(v.x, TR.s[id], Br[m]);
                Bi[m] = fmaf(v.y, TR.s[id], Bi[m]);
            }
        }
    }
    __syncthreads();   // ct8/st8 ready (also separates from any prior use)

    // --- rotate partials: P = cw*A - sw*B, Q = sw*A + cw*B ---
    float pr[17], pi[17], qr[17], qi[17];
#pragma unroll
    for (int m = 0; m < 17; m++) {
        int i8 = (m * w) & 7;
        float cw = ct8[i8], sw = st8[i8];
        pr[m] = cw * Ar[m] - sw * Br[m];
        pi[m] = cw * Ai[m] - sw * Bi[m];
        qr[m] = sw * Ar[m] + cw * Br[m];
        qi[m] = sw * Ai[m] + cw * Bi[m];
    }

    // --- reduce 8 warps -> red[0] ---
    float* rb = red + (size_t)(w & 3) * 2176;
    if (w < 4) {
#pragma unroll
        for (int m = 0; m < 17; m++) {
            rb[m * 128 +       c] = pr[m];
            rb[m * 128 +  32 + c] = pi[m];
            rb[m * 128 +  64 + c] = qr[m];
            rb[m * 128 +  96 + c] = qi[m];
        }
    }
    __syncthreads();
    if (w >= 4) {
#pragma unroll
        for (int m = 0; m < 17; m++) {
            rb[m * 128 +       c] += pr[m];
            rb[m * 128 +  32 + c] += pi[m];
            rb[m * 128 +  64 + c] += qr[m];
            rb[m * 128 +  96 + c] += qi[m];
        }
    }
    __syncthreads();
#pragma unroll
    for (int s = 0; s < 2176; s += 256) {
        int ss = s + t;
        if (ss < 2176)
            red[ss] = red[ss] + red[ss + 2176] + red[ss + 2 * 2176] + red[ss + 3 * 2176];
    }
    __syncthreads();

    // --- assemble X2[h'][c]: h'<=15 -> P - iQ (m=h'); h'>=16 -> P + iQ (m=32-h' or 16)
#pragma unroll
    for (int idx = 0; idx < 1024; idx += 256) {
        int ii = idx + t;
        int h = ii >> 5, cc = ii & 31;
        int m = (h <= 15) ? h : (32 - h);
        if (h == 16) m = 16;
        float Pr = red[m * 128 + cc],      Pi = red[m * 128 + 32 + cc];
        float Qr = red[m * 128 + 64 + cc], Qi = red[m * 128 + 96 + cc];
        if (h <= 15) X2s[ii] = make_float2(Pr + Qi, Pi - Qr);
        else         X2s[ii] = make_float2(Pr - Qi, Pi + Qr);
    }
    __syncthreads();

    // --- einsum: OB[h][o] = sum_c X2[h][c] * Wt[k][h][c][o], scaled ---
    float sc = (k == 0) ? (1.0f / 65536.0f) : (2.0f / 65536.0f);
    const float2* __restrict__ wtk = g_Wt + (size_t)k * 32768;
#pragma unroll
    for (int j = 0; j < 4; j++) {
        int h = w * 4 + j;
        float ar = 0.f, ai = 0.f;
        const float2* __restrict__ xr = X2s + h * 32;
        const float2* __restrict__ wrow = wtk + (size_t)h * 1024 + c;
#pragma unroll
        for (int cc = 0; cc < 32; cc++) {
            float2 xx = xr[cc];
            float2 ww = wrow[cc * 32];
            ar = fmaf(xx.x, ww.x, ar); ar = fmaf(-xx.y, ww.y, ar);
            ai = fmaf(xx.x, ww.y, ai); ai = fmaf( xx.y, ww.x, ai);
        }
        g_OB[(size_t)bk * 1024 + h * 32 + c] = make_float2(ar * sc, ai * sc);
    }
}

// ---------------------------------------------------------------------------
// k2b: inverse H via chunk rotation. Block per bk, 16 warps = (e, q):
//   e = component (re/im), q = y-chunk. Coefficients a,b combined from both
//   corner-mode blocks, rotated by the 8-value table, then 33 FFMA-imm per y.
//   Single code region for ALL warps.
// ---------------------------------------------------------------------------
__global__ void __launch_bounds__(512) k2b_invh() {
    constexpr Trig TR = make_trig();
    __shared__ float ct8[8], st8[8];
    int t = threadIdx.x, w = t >> 5, o = t & 31;
    int e = w & 1, q = w >> 1;
    int bk = blockIdx.x, b = bk >> 4, k = bk & 15;

    if (t < 8) {
        const float cv[8] = {1.f, SQ2H, 0.f, -SQ2H, -1.f, -SQ2H, 0.f, SQ2H};
        const float sv[8] = {0.f, SQ2H, 1.f, SQ2H, 0.f, -SQ2H, -1.f, -SQ2H};
        ct8[t] = cv[t]; st8[t] = sv[t];
    }
    __syncthreads();

    // build a[p], b[p]:  val(y) = sum_p a_p cos(p th) + b_p sin(p th)
    //   U_p = OB[p] (p=0..15, U_16=0), V_p = OB[32-p] (p=1..15), V_16 = OB[16]
    //   e=0: a = Ur+Vr, b = Vi-Ui ;  e=1: a = Ui+Vi, b = Ur-Vr
    const float2* __restrict__ ob = g_OB + (size_t)bk * 1024 + o;
    float a[17], bb[17];
#pragma unroll
    for (int p = 0; p < 17; p++) {
        float Urx = 0.f, Ury = 0.f, Vrx = 0.f, Vry = 0.f;
        if (p <= 15) { float2 U = ob[p * 32]; Urx = U.x; Ury = U.y; }
        if (p >= 1)  { float2 V = ob[(p == 16 ? 16 : 32 - p) * 32]; Vrx = V.x; Vry = V.y; }
        if (e == 0) { a[p] = Urx + Vrx; bb[p] = Vry - Ury; }
        else        { a[p] = Ury + Vry; bb[p] = Urx - Vrx; }
    }

    // rotate by chunk q: alpha = a*cq + b*sq, beta = b*cq - a*sq
#pragma unroll
    for (int p = 0; p < 17; p++) {
        int i8 = (p * q) & 7;
        float cq = ct8[i8], sq = st8[i8];
        float al = a[p] * cq + bb[p] * sq;
        float be = bb[p] * cq - a[p] * sq;
        a[p] = al; bb[p] = be;
    }

    // g_G float view: b*262144 + y*1024 + k*64 + o*2 + e
    float* __restrict__ gf = (float*)g_G + ((size_t)b * 262144 + (size_t)k * 64 + o * 2 + e)
                             + (size_t)(q * 32) * 1024;
#pragma unroll
    for (int u = 0; u < 32; u++) {
        float val = a[0];
#pragma unroll
        for (int p = 1; p < 17; p++) {
            const int id = (p * u) & 255;
            val = fmaf(a[p],  TR.c[id], val);
            val = fmaf(bb[p], TR.s[id], val);
        }
        gf[(size_t)u * 1024] = val;
    }
}

// ---------------------------------------------------------------------------
// k3: inverse W. Block parity selects xp-half (I$-uniform); warp selects row.
// ---------------------------------------------------------------------------
template<int X0, int X1>
__device__ __forceinline__ void invW(const float* __restrict__ Gr,
                                     const float* __restrict__ Gi,
                                     float* __restrict__ ob) {
    constexpr Trig TR = make_trig();
#pragma unroll
    for (int xp = X0; xp < X1; xp++) {
        float A = 0.f, B = 0.f;
#pragma unroll
        for (int k = 0; k < 16; k++) {
            const int id = (k * xp) & 255;
            A = fmaf(Gr[k], TR.c[id], A);
            if (k) B = fmaf(Gi[k], TR.s[id], B);
        }
        ob[xp * 32] = A - B;
        if (xp != 0 && xp != 128)
            ob[(256 - xp) * 32] = A + B;
    }
}

__global__ void __launch_bounds__(256) k3_inv_w(float* __restrict__ out) {
    int t = threadIdx.x, o = t & 31, w = t >> 5;
    int half = blockIdx.x & 1;
    int row = (blockIdx.x >> 1) * 8 + w;
    const float2* __restrict__ g = g_G + (size_t)row * 512 + o;

    float Gr[16], Gi[16];
#pragma unroll
    for (int k = 0; k < 16; k++) { float2 v = g[k * 32]; Gr[k] = v.x; Gi[k] = v.y; }

    float* __restrict__ ob = out + (size_t)row * 8192 + o;
    if (half == 0) invW<0, 65>(Gr, Gi, ob);
    else           invW<65, 129>(Gr, Gi, ob);
}

// ---------------------------------------------------------------------------
extern "C" void kernel_launch(void* const* d_in, const int* in_sizes, int n_in,
                              void* d_out, int out_size) {
    const float* x  = (const float*)d_in[0];
    const float* wr = (const float*)d_in[1];
    const float* wi = (const float*)d_in[2];
    float* out = (float*)d_out;

    k1_fwd_w    <<<256, 256>>>(x);
    k0_reorder_w<<<2048, 256>>>(wr, wi);   // g_Wt into L2 just before k2ac
    k2ac_mid    <<<128, 256>>>();
    k2b_invh    <<<128, 512>>>();
    k3_inv_w    <<<512, 256>>>(out);
}